// round 3
// baseline (speedup 1.0000x reference)
#include <cuda_runtime.h>
#include <cuda_bf16.h>
#include <float.h>

// Problem-size upper bounds (from reference setup_inputs)
#define MAXN 50000
#define MAXE 800000
#define MAXET (MAXE + MAXN)   // + self loops

// ---------------- device scratch (static allocation is allowed) -------------
__device__ float g_hfeat[MAXN * 64];
__device__ float g_hlin [MAXN * 64];
__device__ float g_esrc [MAXN];
__device__ float g_edst [MAXN];
__device__ int   g_hist [MAXN];
__device__ int   g_off  [MAXN + 1];
__device__ int   g_cursor[MAXN];
__device__ int   g_srcs [MAXET];

// ---------------- helpers ---------------------------------------------------
__device__ __forceinline__ float gat_warp_sum(float v) {
#pragma unroll
    for (int o = 16; o; o >>= 1) v += __shfl_xor_sync(0xffffffffu, v, o);
    return v;
}

// ---------------- edge sorting (counting sort by dst) -----------------------
__global__ void gat_zero_kernel(int n) {
    int i = blockIdx.x * blockDim.x + threadIdx.x;
    if (i < n) g_hist[i] = 0;
}

// edge_index is int32 [2, E] row-major: ei[i] = src, ei[E+i] = dst.
__global__ void gat_hist_kernel(const int* __restrict__ ei, int E, int n) {
    int i = blockIdx.x * blockDim.x + threadIdx.x;
    int total = E + n;
    if (i >= total) return;
    int d = (i < E) ? ei[E + i] : (i - E);
    if ((unsigned)d >= (unsigned)n) return;       // defensive
    atomicAdd(&g_hist[d], 1);
}

// single-block exclusive scan of g_hist[0..n) -> g_off, g_cursor; g_off[n]=total
__global__ void gat_scan_kernel(int n) {
    __shared__ int partial[1024];
    int t = threadIdx.x;
    int chunk = (n + 1023) / 1024;
    int begin = t * chunk;
    int endi  = min(begin + chunk, n);
    int sum = 0;
    for (int i = begin; i < endi; i++) sum += g_hist[i];
    partial[t] = sum;
    __syncthreads();
#pragma unroll
    for (int d = 1; d < 1024; d <<= 1) {
        int v = (t >= d) ? partial[t - d] : 0;
        __syncthreads();
        partial[t] += v;
        __syncthreads();
    }
    int run = (t == 0) ? 0 : partial[t - 1];
    for (int i = begin; i < endi; i++) {
        g_off[i]    = run;
        g_cursor[i] = run;
        run += g_hist[i];
    }
    if (t == 0) g_off[n] = partial[1023];
}

__global__ void gat_scatter_kernel(const int* __restrict__ ei, int E, int n) {
    int i = blockIdx.x * blockDim.x + threadIdx.x;
    int total = E + n;
    if (i >= total) return;
    int s, d;
    if (i < E) { s = ei[i]; d = ei[E + i]; }
    else       { s = d = i - E; }
    if ((unsigned)d >= (unsigned)n || (unsigned)s >= (unsigned)n) return;  // defensive
    int pos = atomicAdd(&g_cursor[d], 1);
    g_srcs[pos] = s;
}

// ---------------- tiled GEMM: out = X @ W^T (+bias), optional e_src/e_dst ---
// Block = 256 threads, tile = 32 rows x FOUT cols. Warp w owns rows
// {w, w+8, w+16, w+24}, lanes span all FOUT columns -> warp reductions give
// per-row attention scalars with no atomics.
// SRCSEL: 0 = param X, 1 = g_hfeat.   DSTSEL: 0 = g_hfeat, 1 = g_hlin.
template <int FIN, int FOUT, bool BIAS, bool COMPE, int SRCSEL, int DSTSEL>
__global__ void gat_gemm_kernel(const float* __restrict__ Xparam,
                                const float* __restrict__ W,
                                const float* __restrict__ bias,
                                const float* __restrict__ a_s,
                                const float* __restrict__ a_d,
                                int n) {
    const float* X   = (SRCSEL == 0) ? Xparam : g_hfeat;
    float*       out = (DSTSEL == 0) ? g_hfeat : g_hlin;

    constexpr int COLS = FOUT / 32;   // 2 for FOUT=64, 1 for FOUT=32
    __shared__ float xs[32 * FIN];
    __shared__ float Ws[FIN * FOUT];  // transposed: Ws[k*FOUT + c] = W[c*FIN + k]

    int t  = threadIdx.x;
    int r0 = blockIdx.x * 32;

    for (int idx = t; idx < FIN * FOUT; idx += 256) {
        int k = idx / FOUT, c = idx % FOUT;
        Ws[idx] = W[c * FIN + k];
    }
    for (int idx = t; idx < 32 * FIN; idx += 256) {
        int row = idx / FIN;
        int gr  = r0 + row;
        xs[idx] = (gr < n) ? X[gr * FIN + (idx % FIN)] : 0.f;
    }
    __syncthreads();

    int c  = t & 31;   // lane == column (first half)
    int rg = t >> 5;   // warp id == row group

    float acc[4][COLS];
#pragma unroll
    for (int i = 0; i < 4; i++)
#pragma unroll
        for (int j = 0; j < COLS; j++) acc[i][j] = 0.f;

#pragma unroll 8
    for (int k = 0; k < FIN; k++) {
        float w0 = Ws[k * FOUT + c];
        float w1 = (COLS == 2) ? Ws[k * FOUT + c + 32] : 0.f;
#pragma unroll
        for (int i = 0; i < 4; i++) {
            float xv = xs[(rg + 8 * i) * FIN + k];
            acc[i][0] += xv * w0;
            if (COLS == 2) acc[i][1] += xv * w1;
        }
    }

#pragma unroll
    for (int i = 0; i < 4; i++) {
        int row = rg + 8 * i;
        int gr  = r0 + row;
        float v0 = acc[i][0];
        float v1 = (COLS == 2) ? acc[i][1] : 0.f;
        if (BIAS) {
            v0 += bias[c];
            if (COLS == 2) v1 += bias[c + 32];
        }
        if (gr < n) {
            out[gr * FOUT + c] = v0;
            if (COLS == 2) out[gr * FOUT + 32 + c] = v1;
        }
        if (COMPE) {
            float ps = v0 * a_s[c];
            float pd = v0 * a_d[c];
            if (COLS == 2) {
                ps += v1 * a_s[c + 32];
                pd += v1 * a_d[c + 32];
            }
            ps = gat_warp_sum(ps);
            pd = gat_warp_sum(pd);
            if (c == 0 && gr < n) {
                g_esrc[gr] = ps;
                g_edst[gr] = pd;
            }
        }
    }
}

// ---------------- warp-per-node online-softmax aggregation ------------------
// Edges presorted by dst: node i owns g_srcs[off[i]..off[i+1]). One pass:
// running max m, scaled sum s, scaled feature accumulators. No atomics.
// OUTSEL: 0 = g_hfeat, 1 = param out.
template <int FOUT, bool RELU, bool NORM, int OUTSEL>
__global__ void gat_agg_kernel(const float* __restrict__ bias,
                               float* __restrict__ outparam,
                               int n) {
    const float* hlin = g_hlin;
    float* out = (OUTSEL == 0) ? g_hfeat : outparam;

    int warp = (blockIdx.x * blockDim.x + threadIdx.x) >> 5;
    int lane = threadIdx.x & 31;
    if (warp >= n) return;

    int beg = g_off[warp];
    int end = g_off[warp + 1];
    float ed = g_edst[warp];

    float m = -FLT_MAX;
    float s = 0.f, a0 = 0.f, a1 = 0.f;

    for (int j = beg; j < end; j++) {
        int sv = g_srcs[j];                       // broadcast load
        float e = g_esrc[sv] + ed;                // broadcast gather
        e = (e > 0.f) ? e : 0.2f * e;             // leaky_relu(0.2)
        float mn = fmaxf(m, e);
        float sc = __expf(m - mn);                // first iter: exp(-inf) = 0
        float w  = __expf(e - mn);
        s  = s  * sc + w;
        a0 = a0 * sc + w * hlin[sv * FOUT + lane];
        if (FOUT == 64) a1 = a1 * sc + w * hlin[sv * FOUT + 32 + lane];
        m = mn;
    }

    float inv = 1.f / s;                          // self-loop guarantees s > 0
    float r0 = a0 * inv + bias[lane];
    float r1 = (FOUT == 64) ? a1 * inv + bias[lane + 32] : 0.f;
    if (RELU) { r0 = fmaxf(r0, 0.f); r1 = fmaxf(r1, 0.f); }
    if (NORM) {                                   // FOUT == 32 final layer
        float ss  = gat_warp_sum(r0 * r0);
        float nrm = fmaxf(sqrtf(ss), 1e-12f);
        r0 /= nrm;
    }
    out[warp * FOUT + lane] = r0;
    if (FOUT == 64) out[warp * FOUT + 32 + lane] = r1;
}

// ---------------- launch ----------------------------------------------------
extern "C" void kernel_launch(void* const* d_in, const int* in_sizes, int n_in,
                              void* d_out, int out_size) {
    const float* x    = (const float*)d_in[0];
    const int*   ei   = (const int*)d_in[1];     // int32 [2, E]
    const float* Wpre = (const float*)d_in[2];
    const float* bpre = (const float*)d_in[3];
    const float* W1   = (const float*)d_in[4];
    const float* a1s  = (const float*)d_in[5];
    const float* a1d  = (const float*)d_in[6];
    const float* b1   = (const float*)d_in[7];
    const float* W2   = (const float*)d_in[8];
    const float* a2s  = (const float*)d_in[9];
    const float* a2d  = (const float*)d_in[10];
    const float* b2   = (const float*)d_in[11];
    const float* W3   = (const float*)d_in[12];
    const float* a3s  = (const float*)d_in[13];
    const float* a3d  = (const float*)d_in[14];
    const float* b3   = (const float*)d_in[15];
    float*       out  = (float*)d_out;

    int N = in_sizes[0] / 128;
    int E = in_sizes[1] / 2;
    int ET = E + N;

    // ---- edge sort by dst (counting sort) ----
    gat_zero_kernel<<<(N + 255) / 256, 256>>>(N);
    gat_hist_kernel<<<(ET + 255) / 256, 256>>>(ei, E, N);
    gat_scan_kernel<<<1, 1024>>>(N);
    gat_scatter_kernel<<<(ET + 255) / 256, 256>>>(ei, E, N);

    int gemm_grid = (N + 31) / 32;
    int agg_grid  = (N + 7) / 8;   // 8 warps / block

    // ---- linear_pre: hfeat = x @ Wpre^T + bpre ----
    gat_gemm_kernel<128, 64, true, false, 0, 0><<<gemm_grid, 256>>>(
        x, Wpre, bpre, nullptr, nullptr, N);

    // ---- GAT layer 1 (relu): hlin = hfeat @ W1^T, agg -> hfeat ----
    gat_gemm_kernel<64, 64, false, true, 1, 1><<<gemm_grid, 256>>>(
        nullptr, W1, nullptr, a1s, a1d, N);
    gat_agg_kernel<64, true, false, 0><<<agg_grid, 256>>>(b1, nullptr, N);

    // ---- GAT layer 2 (relu) ----
    gat_gemm_kernel<64, 64, false, true, 1, 1><<<gemm_grid, 256>>>(
        nullptr, W2, nullptr, a2s, a2d, N);
    gat_agg_kernel<64, true, false, 0><<<agg_grid, 256>>>(b2, nullptr, N);

    // ---- GAT layer 3 (+ fused row L2-normalize) -> d_out ----
    gat_gemm_kernel<64, 32, false, true, 1, 1><<<gemm_grid, 256>>>(
        nullptr, W3, nullptr, a3s, a3d, N);
    gat_agg_kernel<32, false, true, 1><<<agg_grid, 256>>>(b3, out, N);
}

// round 4
// speedup vs baseline: 1.4189x; 1.4189x over previous
#include <cuda_runtime.h>
#include <cuda_bf16.h>
#include <float.h>

// Problem-size upper bounds (from reference setup_inputs)
#define MAXN 50000
#define MAXE 800000
#define MAXET (MAXE + MAXN)   // + self loops

// ---------------- device scratch --------------------------------------------
__device__ float g_hfeat[MAXN * 64];
__device__ float g_hlin [MAXN * 64];
__device__ float g_esrc [MAXN];
__device__ float g_edst [MAXN];
__device__ float g_ew   [MAXET];
__device__ int   g_hist [MAXN];
__device__ int   g_off  [MAXN + 1];
__device__ int   g_cursor[MAXN];
__device__ int   g_srcs [MAXET];

// ---------------- helpers ---------------------------------------------------
__device__ __forceinline__ float gat_warp_sum(float v) {
#pragma unroll
    for (int o = 16; o; o >>= 1) v += __shfl_xor_sync(0xffffffffu, v, o);
    return v;
}
__device__ __forceinline__ float gat_warp_max(float v) {
#pragma unroll
    for (int o = 16; o; o >>= 1) v = fmaxf(v, __shfl_xor_sync(0xffffffffu, v, o));
    return v;
}

// ---------------- edge sorting (counting sort by dst) -----------------------
__global__ void gat_zero_kernel(int n) {
    int i = blockIdx.x * blockDim.x + threadIdx.x;
    if (i < n) g_hist[i] = 0;
}

// edge_index is int32 [2, E] row-major: ei[i] = src, ei[E+i] = dst.
__global__ void gat_hist_kernel(const int* __restrict__ ei, int E, int n) {
    int i = blockIdx.x * blockDim.x + threadIdx.x;
    int total = E + n;
    if (i >= total) return;
    int d = (i < E) ? ei[E + i] : (i - E);
    if ((unsigned)d >= (unsigned)n) return;
    atomicAdd(&g_hist[d], 1);
}

__global__ void gat_scan_kernel(int n) {
    __shared__ int partial[1024];
    int t = threadIdx.x;
    int chunk = (n + 1023) / 1024;
    int begin = t * chunk;
    int endi  = min(begin + chunk, n);
    int sum = 0;
    for (int i = begin; i < endi; i++) sum += g_hist[i];
    partial[t] = sum;
    __syncthreads();
#pragma unroll
    for (int d = 1; d < 1024; d <<= 1) {
        int v = (t >= d) ? partial[t - d] : 0;
        __syncthreads();
        partial[t] += v;
        __syncthreads();
    }
    int run = (t == 0) ? 0 : partial[t - 1];
    for (int i = begin; i < endi; i++) {
        g_off[i]    = run;
        g_cursor[i] = run;
        run += g_hist[i];
    }
    if (t == 0) g_off[n] = partial[1023];
}

__global__ void gat_scatter_kernel(const int* __restrict__ ei, int E, int n) {
    int i = blockIdx.x * blockDim.x + threadIdx.x;
    int total = E + n;
    if (i >= total) return;
    int s, d;
    if (i < E) { s = ei[i]; d = ei[E + i]; }
    else       { s = d = i - E; }
    if ((unsigned)d >= (unsigned)n || (unsigned)s >= (unsigned)n) return;
    int pos = atomicAdd(&g_cursor[d], 1);
    g_srcs[pos] = s;
}

// ---------------- tiled GEMM: out = X @ W^T (+bias), optional e_src/e_dst ---
// Block = 256 threads, tile = 32 rows x FOUT cols. Warp w owns rows
// {w, w+8, w+16, w+24}; lanes span columns. XOR-swizzled weight smem:
// Ws[k*FOUT + (c ^ (k&31))] -> conflict-free stores AND loads, no padding.
// SRCSEL: 0 = param X, 1 = g_hfeat.   DSTSEL: 0 = g_hfeat, 1 = g_hlin.
template <int FIN, int FOUT, bool BIAS, bool COMPE, int SRCSEL, int DSTSEL>
__global__ void gat_gemm_kernel(const float* __restrict__ Xparam,
                                const float* __restrict__ W,
                                const float* __restrict__ bias,
                                const float* __restrict__ a_s,
                                const float* __restrict__ a_d,
                                int n) {
    const float* X   = (SRCSEL == 0) ? Xparam : g_hfeat;
    float*       out = (DSTSEL == 0) ? g_hfeat : g_hlin;

    constexpr int COLS = FOUT / 32;   // 2 for FOUT=64, 1 for FOUT=32
    __shared__ float xs[32 * FIN];
    __shared__ float Ws[FIN * FOUT];

    int t  = threadIdx.x;
    int r0 = blockIdx.x * 32;

    // W fill: coalesced global read, swizzled smem write.
    // idx = c*FIN + k (linear over W) -> consecutive threads share c, k consecutive.
    for (int idx = t; idx < FIN * FOUT; idx += 256) {
        int c = idx / FIN, k = idx % FIN;
        Ws[k * FOUT + (c ^ (k & 31))] = W[idx];
    }
    // X fill: float4-vectorized coalesced.
    {
        const float4* X4 = (const float4*)X;
        constexpr int QF = FIN / 4;
        for (int idx = t; idx < 32 * QF; idx += 256) {
            int row = idx / QF, q = idx % QF;
            int gr = r0 + row;
            float4 v = make_float4(0.f, 0.f, 0.f, 0.f);
            if (gr < n) v = X4[gr * QF + q];
            *(float4*)&xs[row * FIN + 4 * q] = v;
        }
    }
    __syncthreads();

    int c  = t & 31;   // lane == column (first half)
    int rg = t >> 5;   // warp id == row group

    float acc[4][COLS];
#pragma unroll
    for (int i = 0; i < 4; i++)
#pragma unroll
        for (int j = 0; j < COLS; j++) acc[i][j] = 0.f;

#pragma unroll 8
    for (int k = 0; k < FIN; k++) {
        int cw = (c ^ (k & 31));
        float w0 = Ws[k * FOUT + cw];
        float w1 = (COLS == 2) ? Ws[k * FOUT + cw + 32] : 0.f;
#pragma unroll
        for (int i = 0; i < 4; i++) {
            float xv = xs[(rg + 8 * i) * FIN + k];
            acc[i][0] += xv * w0;
            if (COLS == 2) acc[i][1] += xv * w1;
        }
    }

#pragma unroll
    for (int i = 0; i < 4; i++) {
        int row = rg + 8 * i;
        int gr  = r0 + row;
        float v0 = acc[i][0];
        float v1 = (COLS == 2) ? acc[i][1] : 0.f;
        if (BIAS) {
            v0 += bias[c];
            if (COLS == 2) v1 += bias[c + 32];
        }
        if (gr < n) {
            out[gr * FOUT + c] = v0;
            if (COLS == 2) out[gr * FOUT + 32 + c] = v1;
        }
        if (COMPE) {
            float ps = v0 * a_s[c];
            float pd = v0 * a_d[c];
            if (COLS == 2) {
                ps += v1 * a_s[c + 32];
                pd += v1 * a_d[c + 32];
            }
            ps = gat_warp_sum(ps);
            pd = gat_warp_sum(pd);
            if (c == 0 && gr < n) {
                g_esrc[gr] = ps;
                g_edst[gr] = pd;
            }
        }
    }
}

// ---------------- warp-per-node two-pass softmax aggregation ----------------
// Pass 1 (lane-parallel): e_j = leaky(esrc[src_j] + edst[i]) -> g_ew, warp max.
// Pass 2: w_j = exp(e_j - m) with NO serial rescale chain; FMA accumulates.
// OUTSEL: 0 = g_hfeat, 1 = param out.
template <int FOUT, bool RELU, bool NORM, int OUTSEL>
__global__ void gat_agg_kernel(const float* __restrict__ bias,
                               float* __restrict__ outparam,
                               int n) {
    const float* hlin = g_hlin;
    float* out = (OUTSEL == 0) ? g_hfeat : outparam;

    int warp = (blockIdx.x * blockDim.x + threadIdx.x) >> 5;
    int lane = threadIdx.x & 31;
    if (warp >= n) return;

    int beg = g_off[warp];
    int end = g_off[warp + 1];
    float ed = g_edst[warp];

    // ---- pass 1: per-edge score + max (lanes stride the edge list) ----
    float lm = -FLT_MAX;
    for (int j = beg + lane; j < end; j += 32) {
        int sv = g_srcs[j];
        float e = g_esrc[sv] + ed;
        e = (e > 0.f) ? e : 0.2f * e;
        g_ew[j] = e;
        lm = fmaxf(lm, e);
    }
    float m = gat_warp_max(lm);
    __threadfence_block();   // make g_ew visible across lanes

    // ---- pass 2: independent exp weights, pipelined gathers ----
    float s = 0.f, a0 = 0.f, a1 = 0.f;
#pragma unroll 4
    for (int j = beg; j < end; j++) {
        int   sv = g_srcs[j];                 // broadcast
        float w  = __expf(g_ew[j] - m);       // broadcast, independent
        s  += w;
        a0 += w * hlin[sv * FOUT + lane];
        if (FOUT == 64) a1 += w * hlin[sv * FOUT + 32 + lane];
    }

    float inv = 1.f / s;                      // self-loop guarantees s > 0
    float r0 = a0 * inv + bias[lane];
    float r1 = (FOUT == 64) ? a1 * inv + bias[lane + 32] : 0.f;
    if (RELU) { r0 = fmaxf(r0, 0.f); r1 = fmaxf(r1, 0.f); }
    if (NORM) {                               // FOUT == 32 final layer
        float ss  = gat_warp_sum(r0 * r0);
        float nrm = fmaxf(sqrtf(ss), 1e-12f);
        r0 /= nrm;
    }
    out[warp * FOUT + lane] = r0;
    if (FOUT == 64) out[warp * FOUT + 32 + lane] = r1;
}

// ---------------- launch ----------------------------------------------------
extern "C" void kernel_launch(void* const* d_in, const int* in_sizes, int n_in,
                              void* d_out, int out_size) {
    const float* x    = (const float*)d_in[0];
    const int*   ei   = (const int*)d_in[1];     // int32 [2, E]
    const float* Wpre = (const float*)d_in[2];
    const float* bpre = (const float*)d_in[3];
    const float* W1   = (const float*)d_in[4];
    const float* a1s  = (const float*)d_in[5];
    const float* a1d  = (const float*)d_in[6];
    const float* b1   = (const float*)d_in[7];
    const float* W2   = (const float*)d_in[8];
    const float* a2s  = (const float*)d_in[9];
    const float* a2d  = (const float*)d_in[10];
    const float* b2   = (const float*)d_in[11];
    const float* W3   = (const float*)d_in[12];
    const float* a3s  = (const float*)d_in[13];
    const float* a3d  = (const float*)d_in[14];
    const float* b3   = (const float*)d_in[15];
    float*       out  = (float*)d_out;

    int N = in_sizes[0] / 128;
    int E = in_sizes[1] / 2;
    int ET = E + N;

    // ---- edge sort by dst (counting sort) ----
    gat_zero_kernel<<<(N + 255) / 256, 256>>>(N);
    gat_hist_kernel<<<(ET + 255) / 256, 256>>>(ei, E, N);
    gat_scan_kernel<<<1, 1024>>>(N);
    gat_scatter_kernel<<<(ET + 255) / 256, 256>>>(ei, E, N);

    int gemm_grid = (N + 31) / 32;
    int agg_grid  = (N + 7) / 8;   // 8 warps / block

    // ---- linear_pre: hfeat = x @ Wpre^T + bpre ----
    gat_gemm_kernel<128, 64, true, false, 0, 0><<<gemm_grid, 256>>>(
        x, Wpre, bpre, nullptr, nullptr, N);

    // ---- GAT layer 1 (relu): hlin = hfeat @ W1^T, agg -> hfeat ----
    gat_gemm_kernel<64, 64, false, true, 1, 1><<<gemm_grid, 256>>>(
        nullptr, W1, nullptr, a1s, a1d, N);
    gat_agg_kernel<64, true, false, 0><<<agg_grid, 256>>>(b1, nullptr, N);

    // ---- GAT layer 2 (relu) ----
    gat_gemm_kernel<64, 64, false, true, 1, 1><<<gemm_grid, 256>>>(
        nullptr, W2, nullptr, a2s, a2d, N);
    gat_agg_kernel<64, true, false, 0><<<agg_grid, 256>>>(b2, nullptr, N);

    // ---- GAT layer 3 (+ fused row L2-normalize) -> d_out ----
    gat_gemm_kernel<64, 32, false, true, 1, 1><<<gemm_grid, 256>>>(
        nullptr, W3, nullptr, a3s, a3d, N);
    gat_agg_kernel<32, false, true, 1><<<agg_grid, 256>>>(b3, out, N);
}

// round 5
// speedup vs baseline: 1.4969x; 1.0550x over previous
#include <cuda_runtime.h>
#include <cuda_bf16.h>
#include <float.h>

// Problem-size upper bounds (from reference setup_inputs)
#define MAXN 50000
#define MAXE 800000
#define MAXET (MAXE + MAXN)   // + self loops

// ---------------- device scratch --------------------------------------------
__device__ float g_hfeat[MAXN * 64];
__device__ float g_hlin [MAXN * 64];
__device__ float g_esrc [MAXN];
__device__ float g_edst [MAXN];
__device__ float g_ew   [MAXET];
__device__ int   g_hist [MAXN];
__device__ int   g_off  [MAXN + 1];
__device__ int   g_cursor[MAXN];
__device__ int   g_srcs [MAXET];

// ---------------- helpers ---------------------------------------------------
__device__ __forceinline__ float gat_warp_sum(float v) {
#pragma unroll
    for (int o = 16; o; o >>= 1) v += __shfl_xor_sync(0xffffffffu, v, o);
    return v;
}
__device__ __forceinline__ float gat_warp_max(float v) {
#pragma unroll
    for (int o = 16; o; o >>= 1) v = fmaxf(v, __shfl_xor_sync(0xffffffffu, v, o));
    return v;
}

// ---------------- edge sorting (counting sort by dst) -----------------------
__global__ void gat_zero_kernel(int n) {
    int i = blockIdx.x * blockDim.x + threadIdx.x;
    if (i < n) g_hist[i] = 0;
}

// edge_index is int32 [2, E] row-major: ei[i] = src, ei[E+i] = dst.
__global__ void gat_hist_kernel(const int* __restrict__ ei, int E, int n) {
    int i = blockIdx.x * blockDim.x + threadIdx.x;
    int total = E + n;
    if (i >= total) return;
    int d = (i < E) ? ei[E + i] : (i - E);
    if ((unsigned)d >= (unsigned)n) return;
    atomicAdd(&g_hist[d], 1);
}

__global__ void gat_scan_kernel(int n) {
    __shared__ int partial[1024];
    int t = threadIdx.x;
    int chunk = (n + 1023) / 1024;
    int begin = t * chunk;
    int endi  = min(begin + chunk, n);
    int sum = 0;
    for (int i = begin; i < endi; i++) sum += g_hist[i];
    partial[t] = sum;
    __syncthreads();
#pragma unroll
    for (int d = 1; d < 1024; d <<= 1) {
        int v = (t >= d) ? partial[t - d] : 0;
        __syncthreads();
        partial[t] += v;
        __syncthreads();
    }
    int run = (t == 0) ? 0 : partial[t - 1];
    for (int i = begin; i < endi; i++) {
        g_off[i]    = run;
        g_cursor[i] = run;
        run += g_hist[i];
    }
    if (t == 0) g_off[n] = partial[1023];
}

__global__ void gat_scatter_kernel(const int* __restrict__ ei, int E, int n) {
    int i = blockIdx.x * blockDim.x + threadIdx.x;
    int total = E + n;
    if (i >= total) return;
    int s, d;
    if (i < E) { s = ei[i]; d = ei[E + i]; }
    else       { s = d = i - E; }
    if ((unsigned)d >= (unsigned)n || (unsigned)s >= (unsigned)n) return;
    int pos = atomicAdd(&g_cursor[d], 1);
    g_srcs[pos] = s;
}

// ---------------- tiled GEMM: out = X @ W^T (+bias), optional e_src/e_dst ---
// Block = 256 threads, tile = ROWS rows x FOUT cols. Warp rg owns rows
// {rg + 8*i}; lanes span columns. W stored c-major with float4 XOR swizzle:
// logical (c, k4) lives at Ws[c*FIN + 4*(k4 ^ (c&7))] -> conflict-free
// float4 fill AND consume. x reads are warp-broadcast float4.
// SRCSEL: 0 = param X, 1 = g_hfeat.   DSTSEL: 0 = g_hfeat, 1 = g_hlin.
template <int FIN, int FOUT, int ROWS, bool BIAS, bool COMPE, int SRCSEL, int DSTSEL>
__global__ void gat_gemm_kernel(const float* __restrict__ Xparam,
                                const float* __restrict__ W,
                                const float* __restrict__ bias,
                                const float* __restrict__ a_s,
                                const float* __restrict__ a_d,
                                int n) {
    const float* X   = (SRCSEL == 0) ? Xparam : g_hfeat;
    float*       out = (DSTSEL == 0) ? g_hfeat : g_hlin;

    constexpr int COLS = FOUT / 32;   // 2 for FOUT=64, 1 for FOUT=32
    constexpr int RPT  = ROWS / 8;    // rows per thread
    constexpr int QF   = FIN / 4;     // float4s per row

    __shared__ float xs[ROWS * FIN];
    __shared__ float Ws[FOUT * FIN];

    int t  = threadIdx.x;
    int r0 = blockIdx.x * ROWS;

    // W fill: coalesced float4 global read, swizzled float4 smem write.
    {
        const float4* W4 = (const float4*)W;
        for (int idx = t; idx < FOUT * QF; idx += 256) {
            int c = idx / QF, k4 = idx % QF;
            *(float4*)&Ws[c * FIN + 4 * (k4 ^ (c & 7))] = W4[idx];
        }
    }
    // X fill: float4-vectorized coalesced.
    {
        const float4* X4 = (const float4*)X;
        for (int idx = t; idx < ROWS * QF; idx += 256) {
            int row = idx / QF, q = idx % QF;
            int gr = r0 + row;
            float4 v = make_float4(0.f, 0.f, 0.f, 0.f);
            if (gr < n) v = X4[gr * QF + q];
            *(float4*)&xs[row * FIN + 4 * q] = v;
        }
    }
    __syncthreads();

    int c  = t & 31;   // lane == column (first half)
    int rg = t >> 5;   // warp id == row group

    float acc[RPT][COLS];
#pragma unroll
    for (int i = 0; i < RPT; i++)
#pragma unroll
        for (int j = 0; j < COLS; j++) acc[i][j] = 0.f;

#pragma unroll 2
    for (int k4 = 0; k4 < QF; k4++) {
        int ks = 4 * (k4 ^ (c & 7));
        float4 w0 = *(const float4*)&Ws[c * FIN + ks];
        float4 w1 = (COLS == 2) ? *(const float4*)&Ws[(c + 32) * FIN + ks]
                                : make_float4(0.f, 0.f, 0.f, 0.f);
#pragma unroll
        for (int i = 0; i < RPT; i++) {
            float4 xv = *(const float4*)&xs[(rg + 8 * i) * FIN + 4 * k4];
            acc[i][0] = fmaf(xv.x, w0.x, acc[i][0]);
            acc[i][0] = fmaf(xv.y, w0.y, acc[i][0]);
            acc[i][0] = fmaf(xv.z, w0.z, acc[i][0]);
            acc[i][0] = fmaf(xv.w, w0.w, acc[i][0]);
            if (COLS == 2) {
                acc[i][1] = fmaf(xv.x, w1.x, acc[i][1]);
                acc[i][1] = fmaf(xv.y, w1.y, acc[i][1]);
                acc[i][1] = fmaf(xv.z, w1.z, acc[i][1]);
                acc[i][1] = fmaf(xv.w, w1.w, acc[i][1]);
            }
        }
    }

#pragma unroll
    for (int i = 0; i < RPT; i++) {
        int row = rg + 8 * i;
        int gr  = r0 + row;
        float v0 = acc[i][0];
        float v1 = (COLS == 2) ? acc[i][1] : 0.f;
        if (BIAS) {
            v0 += bias[c];
            if (COLS == 2) v1 += bias[c + 32];
        }
        if (gr < n) {
            out[gr * FOUT + c] = v0;
            if (COLS == 2) out[gr * FOUT + 32 + c] = v1;
        }
        if (COMPE) {
            float ps = v0 * a_s[c];
            float pd = v0 * a_d[c];
            if (COLS == 2) {
                ps += v1 * a_s[c + 32];
                pd += v1 * a_d[c + 32];
            }
            ps = gat_warp_sum(ps);
            pd = gat_warp_sum(pd);
            if (c == 0 && gr < n) {
                g_esrc[gr] = ps;
                g_edst[gr] = pd;
            }
        }
    }
}

// ---------------- warp-per-node two-pass softmax aggregation ----------------
// Pass 1 (lane-parallel): e_j = leaky(esrc[src_j] + edst[i]) -> g_ew, warp max.
// Pass 2: w_j = exp(e_j - m) with NO serial rescale chain; deep unroll batches
// independent loads (MLP ~16) to hide the sv->hlin dependent-load latency.
// OUTSEL: 0 = g_hfeat, 1 = param out.
template <int FOUT, bool RELU, bool NORM, int OUTSEL>
__global__ void gat_agg_kernel(const float* __restrict__ bias,
                               float* __restrict__ outparam,
                               int n) {
    const float* hlin = g_hlin;
    float* out = (OUTSEL == 0) ? g_hfeat : outparam;

    int warp = (blockIdx.x * blockDim.x + threadIdx.x) >> 5;
    int lane = threadIdx.x & 31;
    if (warp >= n) return;

    int beg = g_off[warp];
    int end = g_off[warp + 1];
    float ed = g_edst[warp];

    // ---- pass 1: per-edge score + max (lanes stride the edge list) ----
    float lm = -FLT_MAX;
    for (int j = beg + lane; j < end; j += 32) {
        int sv = g_srcs[j];
        float e = g_esrc[sv] + ed;
        e = (e > 0.f) ? e : 0.2f * e;
        g_ew[j] = e;
        lm = fmaxf(lm, e);
    }
    float m = gat_warp_max(lm);
    __threadfence_block();   // make g_ew visible across lanes

    // ---- pass 2: independent exp weights, batched gathers ----
    float s = 0.f, a0 = 0.f, a1 = 0.f;
#pragma unroll 8
    for (int j = beg; j < end; j++) {
        int   sv = g_srcs[j];                 // broadcast, L1-hot
        float w  = __expf(g_ew[j] - m);       // broadcast, independent
        s  += w;
        a0 += w * hlin[sv * FOUT + lane];
        if (FOUT == 64) a1 += w * hlin[sv * FOUT + 32 + lane];
    }

    float inv = 1.f / s;                      // self-loop guarantees s > 0
    float r0 = a0 * inv + bias[lane];
    float r1 = (FOUT == 64) ? a1 * inv + bias[lane + 32] : 0.f;
    if (RELU) { r0 = fmaxf(r0, 0.f); r1 = fmaxf(r1, 0.f); }
    if (NORM) {                               // FOUT == 32 final layer
        float ss  = gat_warp_sum(r0 * r0);
        float nrm = fmaxf(sqrtf(ss), 1e-12f);
        r0 /= nrm;
    }
    out[warp * FOUT + lane] = r0;
    if (FOUT == 64) out[warp * FOUT + 32 + lane] = r1;
}

// ---------------- launch ----------------------------------------------------
extern "C" void kernel_launch(void* const* d_in, const int* in_sizes, int n_in,
                              void* d_out, int out_size) {
    const float* x    = (const float*)d_in[0];
    const int*   ei   = (const int*)d_in[1];     // int32 [2, E]
    const float* Wpre = (const float*)d_in[2];
    const float* bpre = (const float*)d_in[3];
    const float* W1   = (const float*)d_in[4];
    const float* a1s  = (const float*)d_in[5];
    const float* a1d  = (const float*)d_in[6];
    const float* b1   = (const float*)d_in[7];
    const float* W2   = (const float*)d_in[8];
    const float* a2s  = (const float*)d_in[9];
    const float* a2d  = (const float*)d_in[10];
    const float* b2   = (const float*)d_in[11];
    const float* W3   = (const float*)d_in[12];
    const float* a3s  = (const float*)d_in[13];
    const float* a3d  = (const float*)d_in[14];
    const float* b3   = (const float*)d_in[15];
    float*       out  = (float*)d_out;

    int N = in_sizes[0] / 128;
    int E = in_sizes[1] / 2;
    int ET = E + N;

    // ---- edge sort by dst (counting sort) ----
    gat_zero_kernel<<<(N + 255) / 256, 256>>>(N);
    gat_hist_kernel<<<(ET + 255) / 256, 256>>>(ei, E, N);
    gat_scan_kernel<<<1, 1024>>>(N);
    gat_scatter_kernel<<<(ET + 255) / 256, 256>>>(ei, E, N);

    int agg_grid = (N + 7) / 8;   // 8 warps / block

    // ---- linear_pre: hfeat = x @ Wpre^T + bpre (ROWS=32: 48KB smem cap) ----
    gat_gemm_kernel<128, 64, 32, true, false, 0, 0><<<(N + 31) / 32, 256>>>(
        x, Wpre, bpre, nullptr, nullptr, N);

    // ---- GAT layer 1 (relu): hlin = hfeat @ W1^T, agg -> hfeat ----
    gat_gemm_kernel<64, 64, 64, false, true, 1, 1><<<(N + 63) / 64, 256>>>(
        nullptr, W1, nullptr, a1s, a1d, N);
    gat_agg_kernel<64, true, false, 0><<<agg_grid, 256>>>(b1, nullptr, N);

    // ---- GAT layer 2 (relu) ----
    gat_gemm_kernel<64, 64, 64, false, true, 1, 1><<<(N + 63) / 64, 256>>>(
        nullptr, W2, nullptr, a2s, a2d, N);
    gat_agg_kernel<64, true, false, 0><<<agg_grid, 256>>>(b2, nullptr, N);

    // ---- GAT layer 3 (+ fused row L2-normalize) -> d_out ----
    gat_gemm_kernel<64, 32, 64, false, true, 1, 1><<<(N + 63) / 64, 256>>>(
        nullptr, W3, nullptr, a3s, a3d, N);
    gat_agg_kernel<32, false, true, 1><<<agg_grid, 256>>>(b3, out, N);
}